// round 2
// baseline (speedup 1.0000x reference)
#include <cuda_runtime.h>

#define BB   2
#define SS   2048
#define DD   1024
#define HH   16
#define HDIM 64
#define MM   (BB*SS)

// Scratch (allocation-free rule: __device__ globals)
__device__ float g_Q[BB*HH*SS*HDIM];   // [b][h][s][c]
__device__ float g_K[BB*HH*SS*HDIM];
__device__ float g_V[BB*HH*SS*HDIM];
__device__ float g_A[MM*DD];           // merged attention output [b*S+s][c*16+h]

// ---------------------------------------------------------------------------
// Shared GEMM body: C_tile(64x64) = X[rowbase:,:] @ W[:,colbase:], K=1024,
// BK=16, 128 threads, per-thread 4x8 microtile.
// Thread map: ty=tid>>3 (16), tx=tid&7 (8). rows = ty+16*rr, cols = tx+8*cc.
// ---------------------------------------------------------------------------
__device__ __forceinline__ void gemm_body(const float* __restrict__ X,
                                          const float* __restrict__ W,
                                          int rowbase, int colbase,
                                          float acc[4][8],
                                          float* Xs, float* Ws,
                                          int ty, int tx, int tid)
{
#pragma unroll
    for (int rr = 0; rr < 4; rr++)
#pragma unroll
        for (int cc = 0; cc < 8; cc++) acc[rr][cc] = 0.f;

    for (int kt = 0; kt < DD; kt += 16) {
        __syncthreads();
#pragma unroll
        for (int i = 0; i < 8; i++) {          // Xs: 64x16, stride 17 (bank-safe)
            int f = tid + i * 128;
            int r = f >> 4, k = f & 15;
            Xs[r * 17 + k] = X[(rowbase + r) * DD + kt + k];
        }
#pragma unroll
        for (int i = 0; i < 8; i++) {          // Ws: 16x64 natural
            int f = tid + i * 128;
            int kr = f >> 6, c = f & 63;
            Ws[f] = W[(kt + kr) * DD + colbase + c];
        }
        __syncthreads();
#pragma unroll
        for (int k = 0; k < 16; k++) {
            float a[4], b[8];
#pragma unroll
            for (int rr = 0; rr < 4; rr++) a[rr] = Xs[(ty + 16 * rr) * 17 + k];
#pragma unroll
            for (int cc = 0; cc < 8; cc++) b[cc] = Ws[k * 64 + tx + 8 * cc];
#pragma unroll
            for (int rr = 0; rr < 4; rr++)
#pragma unroll
                for (int cc = 0; cc < 8; cc++) acc[rr][cc] += a[rr] * b[cc];
        }
    }
}

// ---------------------------------------------------------------------------
// QKV projection. grid = (16, 64, 3). Writes head-split layout:
// column j -> head h=j%16, channel c=j/16  (interleaved split, per reference)
// ---------------------------------------------------------------------------
__global__ __launch_bounds__(128)
void gemm_qkv(const float* __restrict__ X,
              const float* __restrict__ Wq,
              const float* __restrict__ Wk,
              const float* __restrict__ Wv)
{
    __shared__ float Xs[64 * 17];
    __shared__ float Ws[16 * 64];
    int tid = threadIdx.x, ty = tid >> 3, tx = tid & 7;
    int rowbase = blockIdx.y * 64, colbase = blockIdx.x * 64;
    int z = blockIdx.z;
    const float* W = (z == 0) ? Wq : (z == 1 ? Wk : Wv);
    float* dst = (z == 0) ? g_Q : (z == 1 ? g_K : g_V);

    float acc[4][8];
    gemm_body(X, W, rowbase, colbase, acc, Xs, Ws, ty, tx, tid);

#pragma unroll
    for (int rr = 0; rr < 4; rr++)
#pragma unroll
        for (int cc = 0; cc < 8; cc++) {
            int r = rowbase + ty + 16 * rr;
            int j = colbase + tx + 8 * cc;
            int b = r >> 11, s = r & (SS - 1);
            int h = j & 15, c = j >> 4;
            dst[(((b * HH + h) * SS) + s) * HDIM + c] = acc[rr][cc];
        }
}

// ---------------------------------------------------------------------------
// Output projection: out = g_A @ ow. grid = (16, 64).
// ---------------------------------------------------------------------------
__global__ __launch_bounds__(128)
void gemm_out(const float* __restrict__ W, float* __restrict__ out)
{
    __shared__ float Xs[64 * 17];
    __shared__ float Ws[16 * 64];
    int tid = threadIdx.x, ty = tid >> 3, tx = tid & 7;
    int rowbase = blockIdx.y * 64, colbase = blockIdx.x * 64;

    float acc[4][8];
    gemm_body(g_A, W, rowbase, colbase, acc, Xs, Ws, ty, tx, tid);

#pragma unroll
    for (int rr = 0; rr < 4; rr++)
#pragma unroll
        for (int cc = 0; cc < 8; cc++)
            out[(rowbase + ty + 16 * rr) * DD + colbase + tx + 8 * cc] = acc[rr][cc];
}

// ---------------------------------------------------------------------------
// Flash attention, fp32. grid = (32 q-tiles, 32 bh). 128 threads.
// Per CTA: Q tile 64x64, stream K/V blocks of 64 with online softmax.
// smem rows padded to 68 floats (16B-aligned float4, <=2-way conflicts).
// ---------------------------------------------------------------------------
#define PD 68
#define FLASH_SMEM (4 * 64 * PD * (int)sizeof(float))

__global__ __launch_bounds__(128)
void flash_kernel()
{
    extern __shared__ float sm[];
    float* Qs = sm;
    float* Ks = sm + 64 * PD;
    float* Vs = sm + 2 * 64 * PD;
    float* Ps = sm + 3 * 64 * PD;

    int tid = threadIdx.x, ty = tid >> 3, tx = tid & 7;
    int bh = blockIdx.y;
    int b = bh >> 4, h = bh & 15;
    int qt = (int)gridDim.x - 1 - (int)blockIdx.x;   // heaviest tiles first
    int qbase = qt * 64;

    const float* Qg = g_Q + (size_t)bh * SS * HDIM;
    const float* Kg = g_K + (size_t)bh * SS * HDIM;
    const float* Vg = g_V + (size_t)bh * SS * HDIM;

    // Load Q tile (64x64) once
#pragma unroll
    for (int i = 0; i < 8; i++) {
        int f4 = tid + i * 128;            // 1024 float4s
        int r = f4 >> 4, c4 = f4 & 15;
        *reinterpret_cast<float4*>(&Qs[r * PD + c4 * 4]) =
            *reinterpret_cast<const float4*>(&Qg[(qbase + r) * HDIM + c4 * 4]);
    }

    float m[4], l[4], O[4][8];
#pragma unroll
    for (int rr = 0; rr < 4; rr++) {
        m[rr] = -1e30f; l[rr] = 0.f;
#pragma unroll
        for (int dc = 0; dc < 8; dc++) O[rr][dc] = 0.f;
    }

    for (int kb = 0; kb <= qt; kb++) {
        __syncthreads();                           // protect Ks/Vs/Ps reuse
#pragma unroll
        for (int i = 0; i < 8; i++) {
            int f4 = tid + i * 128;
            int r = f4 >> 4, c4 = f4 & 15;
            *reinterpret_cast<float4*>(&Ks[r * PD + c4 * 4]) =
                *reinterpret_cast<const float4*>(&Kg[(kb * 64 + r) * HDIM + c4 * 4]);
            *reinterpret_cast<float4*>(&Vs[r * PD + c4 * 4]) =
                *reinterpret_cast<const float4*>(&Vg[(kb * 64 + r) * HDIM + c4 * 4]);
        }
        __syncthreads();

        // S = Q K^T (thread: rows ty+16rr, cols tx+8cc)
        float sc[4][8];
#pragma unroll
        for (int rr = 0; rr < 4; rr++)
#pragma unroll
            for (int cc = 0; cc < 8; cc++) sc[rr][cc] = 0.f;

#pragma unroll
        for (int d = 0; d < 64; d += 4) {
            float4 q[4], kv[8];
#pragma unroll
            for (int rr = 0; rr < 4; rr++)
                q[rr] = *reinterpret_cast<const float4*>(&Qs[(ty + 16 * rr) * PD + d]);
#pragma unroll
            for (int cc = 0; cc < 8; cc++)
                kv[cc] = *reinterpret_cast<const float4*>(&Ks[(tx + 8 * cc) * PD + d]);
#pragma unroll
            for (int rr = 0; rr < 4; rr++)
#pragma unroll
                for (int cc = 0; cc < 8; cc++)
                    sc[rr][cc] += q[rr].x * kv[cc].x + q[rr].y * kv[cc].y +
                                  q[rr].z * kv[cc].z + q[rr].w * kv[cc].w;
        }

        const float scale = 0.03125f;              // 1/sqrt(1024)
        bool diag = (kb == qt);
#pragma unroll
        for (int rr = 0; rr < 4; rr++)
#pragma unroll
            for (int cc = 0; cc < 8; cc++) {
                float v = sc[rr][cc] * scale;
                if (diag && (kb * 64 + tx + 8 * cc) > (qbase + ty + 16 * rr))
                    v = -1e30f;                    // == ref's -1e10 shift after exp
                sc[rr][cc] = v;
            }

        // online softmax: row max over 8 cc then across the 8 tx lanes
        float mn[4], alpha[4], rs[4];
#pragma unroll
        for (int rr = 0; rr < 4; rr++) {
            float v = sc[rr][0];
#pragma unroll
            for (int cc = 1; cc < 8; cc++) v = fmaxf(v, sc[rr][cc]);
            v = fmaxf(v, __shfl_xor_sync(0xffffffffu, v, 1));
            v = fmaxf(v, __shfl_xor_sync(0xffffffffu, v, 2));
            v = fmaxf(v, __shfl_xor_sync(0xffffffffu, v, 4));
            mn[rr] = fmaxf(m[rr], v);
            alpha[rr] = __expf(m[rr] - mn[rr]);
            rs[rr] = 0.f;
#pragma unroll
            for (int cc = 0; cc < 8; cc++) {
                float p = __expf(sc[rr][cc] - mn[rr]);
                sc[rr][cc] = p;
                rs[rr] += p;
            }
            rs[rr] += __shfl_xor_sync(0xffffffffu, rs[rr], 1);
            rs[rr] += __shfl_xor_sync(0xffffffffu, rs[rr], 2);
            rs[rr] += __shfl_xor_sync(0xffffffffu, rs[rr], 4);
            l[rr] = l[rr] * alpha[rr] + rs[rr];
            m[rr] = mn[rr];
#pragma unroll
            for (int dc = 0; dc < 8; dc++) O[rr][dc] *= alpha[rr];
        }

        // stage P (natural layout [qrow][kcol], stride PD)
#pragma unroll
        for (int rr = 0; rr < 4; rr++)
#pragma unroll
            for (int cc = 0; cc < 8; cc++)
                Ps[(ty + 16 * rr) * PD + tx + 8 * cc] = sc[rr][cc];
        __syncthreads();

        // O += P @ V  (vectorized over k; V columns scalar, conflict-free)
#pragma unroll
        for (int k4 = 0; k4 < 64; k4 += 4) {
            float4 p4[4];
#pragma unroll
            for (int rr = 0; rr < 4; rr++)
                p4[rr] = *reinterpret_cast<const float4*>(&Ps[(ty + 16 * rr) * PD + k4]);
#pragma unroll
            for (int kk = 0; kk < 4; kk++) {
                float vv[8];
#pragma unroll
                for (int dc = 0; dc < 8; dc++)
                    vv[dc] = Vs[(k4 + kk) * PD + tx + 8 * dc];
                float pk[4];
                pk[0] = (kk == 0) ? p4[0].x : (kk == 1) ? p4[0].y : (kk == 2) ? p4[0].z : p4[0].w;
                pk[1] = (kk == 0) ? p4[1].x : (kk == 1) ? p4[1].y : (kk == 2) ? p4[1].z : p4[1].w;
                pk[2] = (kk == 0) ? p4[2].x : (kk == 1) ? p4[2].y : (kk == 2) ? p4[2].z : p4[2].w;
                pk[3] = (kk == 0) ? p4[3].x : (kk == 1) ? p4[3].y : (kk == 2) ? p4[3].z : p4[3].w;
#pragma unroll
                for (int rr = 0; rr < 4; rr++)
#pragma unroll
                    for (int dc = 0; dc < 8; dc++)
                        O[rr][dc] += pk[rr] * vv[dc];
            }
        }
    }

    // epilogue: normalize and write MERGED layout: col j = c*16 + h
#pragma unroll
    for (int rr = 0; rr < 4; rr++) {
        float inv = 1.f / l[rr];
        int sg = qbase + ty + 16 * rr;
#pragma unroll
        for (int dc = 0; dc < 8; dc++) {
            int c = tx + 8 * dc;
            int j = c * 16 + h;
            g_A[((size_t)b * SS + sg) * DD + j] = O[rr][dc] * inv;
        }
    }
}

// ---------------------------------------------------------------------------
extern "C" void kernel_launch(void* const* d_in, const int* in_sizes, int n_in,
                              void* d_out, int out_size)
{
    const float* x  = (const float*)d_in[0];
    const float* qw = (const float*)d_in[1];
    const float* kw = (const float*)d_in[2];
    const float* vw = (const float*)d_in[3];
    const float* ow = (const float*)d_in[4];
    float* out = (float*)d_out;

    cudaFuncSetAttribute(flash_kernel,
                         cudaFuncAttributeMaxDynamicSharedMemorySize, FLASH_SMEM);

    gemm_qkv<<<dim3(DD / 64, MM / 64, 3), 128>>>(x, qw, kw, vw);
    flash_kernel<<<dim3(SS / 64, BB * HH), 128, FLASH_SMEM>>>();
    gemm_out<<<dim3(DD / 64, MM / 64), 128>>>(ow, out);
}

// round 4
// speedup vs baseline: 1.4217x; 1.4217x over previous
#include <cuda_runtime.h>
#include <cuda_bf16.h>
#include <cstdint>

#define BB   2
#define SS   2048
#define DD   1024
#define HH   16
#define HDIM 64
#define MM   (BB*SS)

// ---------------- scratch (__device__ globals; allocation-free rule) -------
__device__ float g_Q[BB*HH*SS*HDIM];   // [b][h][s][c]
__device__ float g_K[BB*HH*SS*HDIM];
__device__ float g_V[BB*HH*SS*HDIM];
__device__ __nv_bfloat16 g_Xh[MM*DD],  g_Xl[MM*DD];       // x split hi/lo
__device__ __nv_bfloat16 g_Wh[4*DD*DD], g_Wl[4*DD*DD];    // W^T (permuted) hi/lo
__device__ __nv_bfloat16 g_Ah[MM*DD],  g_Al[MM*DD];       // attn out split hi/lo

// ---------------- helpers ---------------------------------------------------
__device__ __forceinline__ uint32_t smem_u32(const void* p) {
    uint32_t a;
    asm("{ .reg .u64 t; cvta.to.shared.u64 t, %1; cvt.u32.u64 %0, t; }" : "=r"(a) : "l"(p));
    return a;
}
__device__ __forceinline__ void cp16(uint32_t dst, const void* src) {
    asm volatile("cp.async.ca.shared.global [%0], [%1], 16;" :: "r"(dst), "l"(src));
}
#define CP_COMMIT() asm volatile("cp.async.commit_group;" ::: "memory")
#define CP_WAIT(n)  asm volatile("cp.async.wait_group %0;" :: "n"(n) : "memory")

#define LDSM_X4(r, a)                                                        \
    asm volatile("ldmatrix.sync.aligned.m8n8.x4.shared.b16 {%0,%1,%2,%3}, [%4];" \
        : "=r"((r)[0]), "=r"((r)[1]), "=r"((r)[2]), "=r"((r)[3]) : "r"(a))
#define LDSM_X2(r, a)                                                        \
    asm volatile("ldmatrix.sync.aligned.m8n8.x2.shared.b16 {%0,%1}, [%2];"   \
        : "=r"((r)[0]), "=r"((r)[1]) : "r"(a))

#define MMA16816(d, a, b)                                                    \
    asm volatile("mma.sync.aligned.m16n8k16.row.col.f32.bf16.bf16.f32 "      \
        "{%0,%1,%2,%3}, {%4,%5,%6,%7}, {%8,%9}, {%0,%1,%2,%3};"              \
        : "+f"((d)[0]), "+f"((d)[1]), "+f"((d)[2]), "+f"((d)[3])             \
        : "r"((a)[0]), "r"((a)[1]), "r"((a)[2]), "r"((a)[3]),                \
          "r"((b)[0]), "r"((b)[1]))

// ---------------- prep kernels ---------------------------------------------
__global__ __launch_bounds__(256)
void split_x(const float* __restrict__ x)
{
    int i = blockIdx.x * 256 + threadIdx.x;
    float v = x[i];
    __nv_bfloat16 h = __float2bfloat16(v);
    g_Xh[i] = h;
    g_Xl[i] = __float2bfloat16(v - __bfloat162float(h));
}

// W^T with head-permuted columns for QKV (z<3): row j' = h*64+ch where source
// col j = ch*16+h  (so j' = (j&15)*64 + (j>>4)); z==3 (ow): plain transpose.
__global__ void prep_w(const float* __restrict__ qw, const float* __restrict__ kw,
                       const float* __restrict__ vw, const float* __restrict__ ow)
{
    __shared__ float tile[32][33];
    int z = blockIdx.z;
    const float* W = (z == 0) ? qw : (z == 1) ? kw : (z == 2) ? vw : ow;
    int kbase = blockIdx.y * 32, jbase = blockIdx.x * 32;
    int tx = threadIdx.x, ty = threadIdx.y;
    tile[ty][tx] = W[(kbase + ty) * DD + jbase + tx];
    __syncthreads();
    int j = jbase + ty;
    int jp = (z < 3) ? ((j & 15) * 64 + (j >> 4)) : j;
    float v = tile[tx][ty];                 // = W[kbase+tx][j]
    __nv_bfloat16 h = __float2bfloat16(v);
    size_t o = (size_t)z * DD * DD + (size_t)jp * DD + kbase + tx;
    g_Wh[o] = h;
    g_Wl[o] = __float2bfloat16(v - __bfloat162float(h));
}

// ---------------- mma.sync GEMM mainloop ------------------------------------
// C[128x128] = (Ah+Al)[rowbase..][:] * (Bh+Bl)[colbase..][:]^T, K=1024, BK=32.
// 256 threads = 8 warps (2m x 4n), warp tile 64x32, 2-stage cp.async pipeline.
// smem per matrix per stage: 128 rows x 80B (32 bf16 + 16B pad) = 10240 B.
// Row stride 80B => 8 ldmatrix rows hit 8 disjoint 4-bank groups (conflict-free).
#define STAGE_B 40960
#define GSMEM   (2 * STAGE_B)
#define NITER   (DD / 32)

__device__ __forceinline__ void load_stage(
    uint32_t sb, int s, int kt,
    const __nv_bfloat16* __restrict__ Ah, const __nv_bfloat16* __restrict__ Al,
    const __nv_bfloat16* __restrict__ Bh, const __nv_bfloat16* __restrict__ Bl,
    int rowbase, int colbase, int tid)
{
    uint32_t base = sb + s * STAGE_B;
#pragma unroll
    for (int t = 0; t < 8; t++) {
        int f = tid + t * 256;
        int mat = f >> 9;                 // 0:Ah 1:Al 2:Bh 3:Bl
        int w = f & 511;
        int r = w >> 2, c = w & 3;        // row 0-127, 16B chunk 0-3
        int rb = (mat < 2) ? rowbase : colbase;
        const __nv_bfloat16* src = ((mat == 0) ? Ah : (mat == 1) ? Al :
                                    (mat == 2) ? Bh : Bl) +
                                   (size_t)(rb + r) * DD + kt + c * 8;
        cp16(base + mat * 10240 + r * 80 + c * 16, src);
    }
}

__device__ __forceinline__ void gemm_mainloop_mma(
    const __nv_bfloat16* __restrict__ Ah, const __nv_bfloat16* __restrict__ Al,
    const __nv_bfloat16* __restrict__ Bh, const __nv_bfloat16* __restrict__ Bl,
    int rowbase, int colbase, char* smem, float d[4][4][4])
{
    uint32_t sb = smem_u32(smem);
    int tid = threadIdx.x;
    int lane = tid & 31, warp = tid >> 5;
    int wm = warp >> 2, wn = warp & 3;

#pragma unroll
    for (int mt = 0; mt < 4; mt++)
#pragma unroll
        for (int nt = 0; nt < 4; nt++)
#pragma unroll
            for (int e = 0; e < 4; e++) d[mt][nt][e] = 0.f;

    load_stage(sb, 0, 0, Ah, Al, Bh, Bl, rowbase, colbase, tid);
    CP_COMMIT();

    int idq = lane >> 3;                  // ldmatrix matrix id (0-3)
    for (int it = 0; it < NITER; it++) {
        if (it + 1 < NITER) {
            load_stage(sb, (it + 1) & 1, (it + 1) * 32, Ah, Al, Bh, Bl,
                       rowbase, colbase, tid);
            CP_COMMIT();
            CP_WAIT(1);
        } else {
            CP_WAIT(0);
        }
        __syncthreads();
        uint32_t st = sb + (it & 1) * STAGE_B;
#pragma unroll
        for (int ks = 0; ks < 2; ks++) {
            uint32_t ah[4][4], al[4][4], bh[4][2], bl[4][2];
#pragma unroll
            for (int mt = 0; mt < 4; mt++) {
                int row = wm * 64 + mt * 16 + (idq & 1) * 8 + (lane & 7);
                int kk = ks * 16 + (idq >> 1) * 8;
                uint32_t a = st + row * 80 + kk * 2;
                LDSM_X4(ah[mt], a);
                LDSM_X4(al[mt], a + 10240);
            }
#pragma unroll
            for (int nt = 0; nt < 4; nt++) {
                int n = wn * 32 + nt * 8 + (lane & 7);
                int kk = ks * 16 + ((lane >> 3) & 1) * 8;
                uint32_t a = st + 20480 + n * 80 + kk * 2;
                LDSM_X2(bh[nt], a);
                LDSM_X2(bl[nt], a + 10240);
            }
#pragma unroll
            for (int mt = 0; mt < 4; mt++)
#pragma unroll
                for (int nt = 0; nt < 4; nt++) {
                    MMA16816(d[mt][nt], ah[mt], bh[nt]);
                    MMA16816(d[mt][nt], ah[mt], bl[nt]);
                    MMA16816(d[mt][nt], al[mt], bh[nt]);
                }
        }
        __syncthreads();
    }
}

// ---------------- QKV projection -------------------------------------------
__global__ __launch_bounds__(256, 1)
void gemm_qkv_mma()
{
    extern __shared__ char smem[];
    int z = blockIdx.z;
    int rowbase = blockIdx.y * 128, colbase = blockIdx.x * 128;
    const __nv_bfloat16* Bh = g_Wh + (size_t)z * DD * DD;
    const __nv_bfloat16* Bl = g_Wl + (size_t)z * DD * DD;
    float* dst = (z == 0) ? g_Q : (z == 1) ? g_K : g_V;

    float d[4][4][4];
    gemm_mainloop_mma(g_Xh, g_Xl, Bh, Bl, rowbase, colbase, smem, d);

    int lane = threadIdx.x & 31, warp = threadIdx.x >> 5;
    int wm = warp >> 2, wn = warp & 3;
#pragma unroll
    for (int mt = 0; mt < 4; mt++) {
        int m0 = rowbase + wm * 64 + mt * 16 + (lane >> 2);
#pragma unroll
        for (int nt = 0; nt < 4; nt++) {
            int j = colbase + wn * 32 + nt * 8 + (lane & 3) * 2;   // permuted col
            int h = j >> 6, c = j & 63;
#pragma unroll
            for (int rr = 0; rr < 2; rr++) {
                int m = m0 + rr * 8;
                int b = m >> 11, s = m & (SS - 1);
                float2 v = make_float2(d[mt][nt][rr * 2], d[mt][nt][rr * 2 + 1]);
                *reinterpret_cast<float2*>(
                    dst + (((size_t)(b * HH + h) * SS + s) * HDIM + c)) = v;
            }
        }
    }
}

// ---------------- output projection ----------------------------------------
__global__ __launch_bounds__(256, 1)
void gemm_out_mma(float* __restrict__ out)
{
    extern __shared__ char smem[];
    int rowbase = blockIdx.y * 128, colbase = blockIdx.x * 128;
    const __nv_bfloat16* Bh = g_Wh + (size_t)3 * DD * DD;
    const __nv_bfloat16* Bl = g_Wl + (size_t)3 * DD * DD;

    float d[4][4][4];
    gemm_mainloop_mma(g_Ah, g_Al, Bh, Bl, rowbase, colbase, smem, d);

    int lane = threadIdx.x & 31, warp = threadIdx.x >> 5;
    int wm = warp >> 2, wn = warp & 3;
#pragma unroll
    for (int mt = 0; mt < 4; mt++) {
        int m0 = rowbase + wm * 64 + mt * 16 + (lane >> 2);
#pragma unroll
        for (int nt = 0; nt < 4; nt++) {
            int j = colbase + wn * 32 + nt * 8 + (lane & 3) * 2;
#pragma unroll
            for (int rr = 0; rr < 2; rr++) {
                int m = m0 + rr * 8;
                float2 v = make_float2(d[mt][nt][rr * 2], d[mt][nt][rr * 2 + 1]);
                *reinterpret_cast<float2*>(out + (size_t)m * DD + j) = v;
            }
        }
    }
}

// ---------------- flash attention (fp32 SIMT, proven) -----------------------
#define PD 68
#define FLASH_SMEM (4 * 64 * PD * (int)sizeof(float))

__global__ __launch_bounds__(128)
void flash_kernel()
{
    extern __shared__ float sm[];
    float* Qs = sm;
    float* Ks = sm + 64 * PD;
    float* Vs = sm + 2 * 64 * PD;
    float* Ps = sm + 3 * 64 * PD;

    int tid = threadIdx.x, ty = tid >> 3, tx = tid & 7;
    int bh = blockIdx.y;
    int b = bh >> 4, h = bh & 15;
    int qt = (int)gridDim.x - 1 - (int)blockIdx.x;
    int qbase = qt * 64;

    const float* Qg = g_Q + (size_t)bh * SS * HDIM;
    const float* Kg = g_K + (size_t)bh * SS * HDIM;
    const float* Vg = g_V + (size_t)bh * SS * HDIM;

#pragma unroll
    for (int i = 0; i < 8; i++) {
        int f4 = tid + i * 128;
        int r = f4 >> 4, c4 = f4 & 15;
        *reinterpret_cast<float4*>(&Qs[r * PD + c4 * 4]) =
            *reinterpret_cast<const float4*>(&Qg[(qbase + r) * HDIM + c4 * 4]);
    }

    float m[4], l[4], O[4][8];
#pragma unroll
    for (int rr = 0; rr < 4; rr++) {
        m[rr] = -1e30f; l[rr] = 0.f;
#pragma unroll
        for (int dc = 0; dc < 8; dc++) O[rr][dc] = 0.f;
    }

    for (int kb = 0; kb <= qt; kb++) {
        __syncthreads();
#pragma unroll
        for (int i = 0; i < 8; i++) {
            int f4 = tid + i * 128;
            int r = f4 >> 4, c4 = f4 & 15;
            *reinterpret_cast<float4*>(&Ks[r * PD + c4 * 4]) =
                *reinterpret_cast<const float4*>(&Kg[(kb * 64 + r) * HDIM + c4 * 4]);
            *reinterpret_cast<float4*>(&Vs[r * PD + c4 * 4]) =
                *reinterpret_cast<const float4*>(&Vg[(kb * 64 + r) * HDIM + c4 * 4]);
        }
        __syncthreads();

        float sc[4][8];
#pragma unroll
        for (int rr = 0; rr < 4; rr++)
#pragma unroll
            for (int cc = 0; cc < 8; cc++) sc[rr][cc] = 0.f;

#pragma unroll
        for (int dd = 0; dd < 64; dd += 4) {
            float4 q[4], kv[8];
#pragma unroll
            for (int rr = 0; rr < 4; rr++)
                q[rr] = *reinterpret_cast<const float4*>(&Qs[(ty + 16 * rr) * PD + dd]);
#pragma unroll
            for (int cc = 0; cc < 8; cc++)
                kv[cc] = *reinterpret_cast<const float4*>(&Ks[(tx + 8 * cc) * PD + dd]);
#pragma unroll
            for (int rr = 0; rr < 4; rr++)
#pragma unroll
                for (int cc = 0; cc < 8; cc++)
                    sc[rr][cc] += q[rr].x * kv[cc].x + q[rr].y * kv[cc].y +
                                  q[rr].z * kv[cc].z + q[rr].w * kv[cc].w;
        }

        const float scale = 0.03125f;
        bool diag = (kb == qt);
#pragma unroll
        for (int rr = 0; rr < 4; rr++)
#pragma unroll
            for (int cc = 0; cc < 8; cc++) {
                float v = sc[rr][cc] * scale;
                if (diag && (kb * 64 + tx + 8 * cc) > (qbase + ty + 16 * rr))
                    v = -1e30f;
                sc[rr][cc] = v;
            }

        float mn[4], alpha[4], rs[4];
#pragma unroll
        for (int rr = 0; rr < 4; rr++) {
            float v = sc[rr][0];
#pragma unroll
            for (int cc = 1; cc < 8; cc++) v = fmaxf(v, sc[rr][cc]);
            v = fmaxf(v, __shfl_xor_sync(0xffffffffu, v, 1));
            v = fmaxf(v, __shfl_xor_sync(0xffffffffu, v, 2));
            v = fmaxf(v, __shfl_xor_sync(0xffffffffu, v, 4));
            mn[rr] = fmaxf(m[rr], v);
            alpha[rr] = __expf(m[rr] - mn[rr]);
            rs[rr] = 0.f;
#pragma unroll
            for (int cc = 0; cc < 8; cc++) {
                float p = __expf(sc[rr][cc] - mn[rr]);
                sc[rr][cc] = p;
                rs[rr] += p;
            }
            rs[rr] += __shfl_xor_sync(0xffffffffu, rs[rr], 1);
            rs[rr] += __shfl_xor_sync(0xffffffffu, rs[rr], 2);
            rs[rr] += __shfl_xor_sync(0xffffffffu, rs[rr], 4);
            l[rr] = l[rr] * alpha[rr] + rs[rr];
            m[rr] = mn[rr];
#pragma unroll
            for (int dc = 0; dc < 8; dc++) O[rr][dc] *= alpha[rr];
        }

#pragma unroll
        for (int rr = 0; rr < 4; rr++)
#pragma unroll
            for (int cc = 0; cc < 8; cc++)
                Ps[(ty + 16 * rr) * PD + tx + 8 * cc] = sc[rr][cc];
        __syncthreads();

#pragma unroll
        for (int k4 = 0; k4 < 64; k4 += 4) {
            float4 p4[4];
#pragma unroll
            for (int rr = 0; rr < 4; rr++)
                p4[rr] = *reinterpret_cast<const float4*>(&Ps[(ty + 16 * rr) * PD + k4]);
#pragma unroll
            for (int kk = 0; kk < 4; kk++) {
                float vv[8];
#pragma unroll
                for (int dc = 0; dc < 8; dc++)
                    vv[dc] = Vs[(k4 + kk) * PD + tx + 8 * dc];
                float pk[4];
                pk[0] = (kk == 0) ? p4[0].x : (kk == 1) ? p4[0].y : (kk == 2) ? p4[0].z : p4[0].w;
                pk[1] = (kk == 0) ? p4[1].x : (kk == 1) ? p4[1].y : (kk == 2) ? p4[1].z : p4[1].w;
                pk[2] = (kk == 0) ? p4[2].x : (kk == 1) ? p4[2].y : (kk == 2) ? p4[2].z : p4[2].w;
                pk[3] = (kk == 0) ? p4[3].x : (kk == 1) ? p4[3].y : (kk == 2) ? p4[3].z : p4[3].w;
#pragma unroll
                for (int rr = 0; rr < 4; rr++)
#pragma unroll
                    for (int dc = 0; dc < 8; dc++)
                        O[rr][dc] += pk[rr] * vv[dc];
            }
        }
    }

    // epilogue: normalize, MERGED layout col j = c*16 + h, split into bf16 hi/lo
#pragma unroll
    for (int rr = 0; rr < 4; rr++) {
        float inv = 1.f / l[rr];
        int sg = qbase + ty + 16 * rr;
#pragma unroll
        for (int dc = 0; dc < 8; dc++) {
            int c = tx + 8 * dc;
            int j = c * 16 + h;
            size_t idx = ((size_t)b * SS + sg) * DD + j;
            float v = O[rr][dc] * inv;
            __nv_bfloat16 hv = __float2bfloat16(v);
            g_Ah[idx] = hv;
            g_Al[idx] = __float2bfloat16(v - __bfloat162float(hv));
        }
    }
}

// ---------------------------------------------------------------------------
extern "C" void kernel_launch(void* const* d_in, const int* in_sizes, int n_in,
                              void* d_out, int out_size)
{
    const float* x  = (const float*)d_in[0];
    const float* qw = (const float*)d_in[1];
    const float* kw = (const float*)d_in[2];
    const float* vw = (const float*)d_in[3];
    const float* ow = (const float*)d_in[4];
    float* out = (float*)d_out;

    cudaFuncSetAttribute(flash_kernel,
                         cudaFuncAttributeMaxDynamicSharedMemorySize, FLASH_SMEM);
    cudaFuncSetAttribute(gemm_qkv_mma,
                         cudaFuncAttributeMaxDynamicSharedMemorySize, GSMEM);
    cudaFuncSetAttribute(gemm_out_mma,
                         cudaFuncAttributeMaxDynamicSharedMemorySize, GSMEM);

    split_x<<<MM * DD / 256, 256>>>(x);
    prep_w<<<dim3(DD / 32, DD / 32, 4), dim3(32, 32)>>>(qw, kw, vw, ow);
    gemm_qkv_mma<<<dim3(DD / 128, MM / 128, 3), 256, GSMEM>>>();
    flash_kernel<<<dim3(SS / 64, BB * HH), 128, FLASH_SMEM>>>();
    gemm_out_mma<<<dim3(DD / 128, MM / 128), 256, GSMEM>>>(out);
}

// round 5
// speedup vs baseline: 3.1300x; 2.2016x over previous
#include <cuda_runtime.h>
#include <cuda_bf16.h>
#include <cstdint>

#define BB   2
#define SS   2048
#define DD   1024
#define HH   16
#define HDIM 64
#define MM   (BB*SS)

// ---------------- scratch (__device__ globals; allocation-free rule) -------
__device__ __nv_bfloat16 g_Qh[BB*HH*SS*HDIM], g_Ql[BB*HH*SS*HDIM];  // [bh][s][c], pre-scaled 1/32
__device__ __nv_bfloat16 g_Kh[BB*HH*SS*HDIM], g_Kl[BB*HH*SS*HDIM];  // [bh][s][c]
__device__ __nv_bfloat16 g_Vth[BB*HH*SS*HDIM], g_Vtl[BB*HH*SS*HDIM];// [bh][c][s] transposed
__device__ __nv_bfloat16 g_Xh[MM*DD],  g_Xl[MM*DD];                 // x split hi/lo
__device__ __nv_bfloat16 g_Wh[4*DD*DD], g_Wl[4*DD*DD];              // W^T (permuted) hi/lo
__device__ __nv_bfloat16 g_Ah[MM*DD],  g_Al[MM*DD];                 // attn out [b][s][h*64+c]

// ---------------- helpers ---------------------------------------------------
__device__ __forceinline__ uint32_t smem_u32(const void* p) {
    uint32_t a;
    asm("{ .reg .u64 t; cvta.to.shared.u64 t, %1; cvt.u32.u64 %0, t; }" : "=r"(a) : "l"(p));
    return a;
}
__device__ __forceinline__ void cp16(uint32_t dst, const void* src) {
    asm volatile("cp.async.ca.shared.global [%0], [%1], 16;" :: "r"(dst), "l"(src));
}
#define CP_COMMIT() asm volatile("cp.async.commit_group;" ::: "memory")
#define CP_WAIT(n)  asm volatile("cp.async.wait_group %0;" :: "n"(n) : "memory")

#define LDSM_X4(r, a)                                                        \
    asm volatile("ldmatrix.sync.aligned.m8n8.x4.shared.b16 {%0,%1,%2,%3}, [%4];" \
        : "=r"((r)[0]), "=r"((r)[1]), "=r"((r)[2]), "=r"((r)[3]) : "r"(a))
#define LDSM_X2(r, a)                                                        \
    asm volatile("ldmatrix.sync.aligned.m8n8.x2.shared.b16 {%0,%1}, [%2];"   \
        : "=r"((r)[0]), "=r"((r)[1]) : "r"(a))

#define MMA16816(d, a, b)                                                    \
    asm volatile("mma.sync.aligned.m16n8k16.row.col.f32.bf16.bf16.f32 "      \
        "{%0,%1,%2,%3}, {%4,%5,%6,%7}, {%8,%9}, {%0,%1,%2,%3};"              \
        : "+f"((d)[0]), "+f"((d)[1]), "+f"((d)[2]), "+f"((d)[3])             \
        : "r"((a)[0]), "r"((a)[1]), "r"((a)[2]), "r"((a)[3]),                \
          "r"((b)[0]), "r"((b)[1]))

// split v0,v1 into bf16 hi (returned packed) and lo (out param packed)
__device__ __forceinline__ uint32_t split_pack(float v0, float v1, uint32_t& lo) {
    __nv_bfloat16 h0 = __float2bfloat16(v0), h1 = __float2bfloat16(v1);
    __nv_bfloat16 l0 = __float2bfloat16(v0 - __bfloat162float(h0));
    __nv_bfloat16 l1 = __float2bfloat16(v1 - __bfloat162float(h1));
    __nv_bfloat162 hp, lp;
    hp.x = h0; hp.y = h1; lp.x = l0; lp.y = l1;
    lo = *reinterpret_cast<uint32_t*>(&lp);
    return *reinterpret_cast<uint32_t*>(&hp);
}

// ---------------- prep kernels ---------------------------------------------
__global__ __launch_bounds__(256)
void split_x(const float* __restrict__ x)
{
    int i = blockIdx.x * 256 + threadIdx.x;
    float v = x[i];
    __nv_bfloat16 h = __float2bfloat16(v);
    g_Xh[i] = h;
    g_Xl[i] = __float2bfloat16(v - __bfloat162float(h));
}

// z<3 (qw,kw,vw): W^T with head-permuted columns: dst row j' = h*64+ch for
//   source col j = ch*16+h  (j' = (j&15)*64 + (j>>4)).
// z==3 (ow): W^T with permuted k (contraction) index: dst col k' = (k&15)*64 + (k>>4)
//   so the out-GEMM consumes attention scratch in natural [h*64+c] order.
__global__ void prep_w(const float* __restrict__ qw, const float* __restrict__ kw,
                       const float* __restrict__ vw, const float* __restrict__ ow)
{
    __shared__ float tile[32][33];
    int z = blockIdx.z;
    const float* W = (z == 0) ? qw : (z == 1) ? kw : (z == 2) ? vw : ow;
    int kbase = blockIdx.y * 32, jbase = blockIdx.x * 32;
    int tx = threadIdx.x, ty = threadIdx.y;
    tile[ty][tx] = W[(kbase + ty) * DD + jbase + tx];
    __syncthreads();
    int j = jbase + ty;
    int k = kbase + tx;
    float v = tile[tx][ty];                 // = W[k][j]
    __nv_bfloat16 h = __float2bfloat16(v);
    size_t o;
    if (z < 3) {
        int jp = (j & 15) * 64 + (j >> 4);
        o = (size_t)z * DD * DD + (size_t)jp * DD + k;
    } else {
        int kp = (k & 15) * 64 + (k >> 4);
        o = (size_t)3 * DD * DD + (size_t)j * DD + kp;
    }
    g_Wh[o] = h;
    g_Wl[o] = __float2bfloat16(v - __bfloat162float(h));
}

// ---------------- mma.sync GEMM mainloop (proven round-4) -------------------
#define STAGE_B 40960
#define GSMEM   (2 * STAGE_B)
#define NITER   (DD / 32)

__device__ __forceinline__ void load_stage(
    uint32_t sb, int s, int kt,
    const __nv_bfloat16* __restrict__ Ah, const __nv_bfloat16* __restrict__ Al,
    const __nv_bfloat16* __restrict__ Bh, const __nv_bfloat16* __restrict__ Bl,
    int rowbase, int colbase, int tid)
{
    uint32_t base = sb + s * STAGE_B;
#pragma unroll
    for (int t = 0; t < 8; t++) {
        int f = tid + t * 256;
        int mat = f >> 9;
        int w = f & 511;
        int r = w >> 2, c = w & 3;
        int rb = (mat < 2) ? rowbase : colbase;
        const __nv_bfloat16* src = ((mat == 0) ? Ah : (mat == 1) ? Al :
                                    (mat == 2) ? Bh : Bl) +
                                   (size_t)(rb + r) * DD + kt + c * 8;
        cp16(base + mat * 10240 + r * 80 + c * 16, src);
    }
}

__device__ __forceinline__ void gemm_mainloop_mma(
    const __nv_bfloat16* __restrict__ Ah, const __nv_bfloat16* __restrict__ Al,
    const __nv_bfloat16* __restrict__ Bh, const __nv_bfloat16* __restrict__ Bl,
    int rowbase, int colbase, char* smem, float d[4][4][4])
{
    uint32_t sb = smem_u32(smem);
    int tid = threadIdx.x;
    int lane = tid & 31, warp = tid >> 5;
    int wm = warp >> 2, wn = warp & 3;

#pragma unroll
    for (int mt = 0; mt < 4; mt++)
#pragma unroll
        for (int nt = 0; nt < 4; nt++)
#pragma unroll
            for (int e = 0; e < 4; e++) d[mt][nt][e] = 0.f;

    load_stage(sb, 0, 0, Ah, Al, Bh, Bl, rowbase, colbase, tid);
    CP_COMMIT();

    int idq = lane >> 3;
    for (int it = 0; it < NITER; it++) {
        if (it + 1 < NITER) {
            load_stage(sb, (it + 1) & 1, (it + 1) * 32, Ah, Al, Bh, Bl,
                       rowbase, colbase, tid);
            CP_COMMIT();
            CP_WAIT(1);
        } else {
            CP_WAIT(0);
        }
        __syncthreads();
        uint32_t st = sb + (it & 1) * STAGE_B;
#pragma unroll
        for (int ks = 0; ks < 2; ks++) {
            uint32_t ah[4][4], al[4][4], bh[4][2], bl[4][2];
#pragma unroll
            for (int mt = 0; mt < 4; mt++) {
                int row = wm * 64 + mt * 16 + (idq & 1) * 8 + (lane & 7);
                int kk = ks * 16 + (idq >> 1) * 8;
                uint32_t a = st + row * 80 + kk * 2;
                LDSM_X4(ah[mt], a);
                LDSM_X4(al[mt], a + 10240);
            }
#pragma unroll
            for (int nt = 0; nt < 4; nt++) {
                int n = wn * 32 + nt * 8 + (lane & 7);
                int kk = ks * 16 + ((lane >> 3) & 1) * 8;
                uint32_t a = st + 20480 + n * 80 + kk * 2;
                LDSM_X2(bh[nt], a);
                LDSM_X2(bl[nt], a + 10240);
            }
#pragma unroll
            for (int mt = 0; mt < 4; mt++)
#pragma unroll
                for (int nt = 0; nt < 4; nt++) {
                    MMA16816(d[mt][nt], ah[mt], bh[nt]);
                    MMA16816(d[mt][nt], ah[mt], bl[nt]);
                    MMA16816(d[mt][nt], al[mt], bh[nt]);
                }
        }
        __syncthreads();
    }
}

// ---------------- QKV projection -------------------------------------------
__global__ __launch_bounds__(256, 1)
void gemm_qkv_mma()
{
    extern __shared__ char smem[];
    int z = blockIdx.z;
    int rowbase = blockIdx.y * 128, colbase = blockIdx.x * 128;
    const __nv_bfloat16* Bh = g_Wh + (size_t)z * DD * DD;
    const __nv_bfloat16* Bl = g_Wl + (size_t)z * DD * DD;

    float d[4][4][4];
    gemm_mainloop_mma(g_Xh, g_Xl, Bh, Bl, rowbase, colbase, smem, d);

    int lane = threadIdx.x & 31, warp = threadIdx.x >> 5;
    int wm = warp >> 2, wn = warp & 3;
    float scale = (z == 0) ? 0.03125f : 1.0f;     // fold 1/sqrt(D) into Q (exact)

#pragma unroll
    for (int mt = 0; mt < 4; mt++) {
        int m0 = rowbase + wm * 64 + mt * 16 + (lane >> 2);
#pragma unroll
        for (int nt = 0; nt < 4; nt++) {
            int j = colbase + wn * 32 + nt * 8 + (lane & 3) * 2;   // head-major col
            int hh = j >> 6, cc = j & 63;
#pragma unroll
            for (int rr = 0; rr < 2; rr++) {
                int m = m0 + rr * 8;
                int b = m >> 11, sI = m & (SS - 1);
                float v0 = d[mt][nt][rr * 2] * scale;
                float v1 = d[mt][nt][rr * 2 + 1] * scale;
                if (z == 2) {
                    // V transposed: [bh][c][s], 2B scattered (epilogue only)
                    __nv_bfloat16 h0 = __float2bfloat16(v0);
                    __nv_bfloat16 h1 = __float2bfloat16(v1);
                    size_t o0 = ((size_t)((b * HH + hh) * HDIM + cc)) * SS + sI;
                    size_t o1 = ((size_t)((b * HH + hh) * HDIM + cc + 1)) * SS + sI;
                    g_Vth[o0] = h0;
                    g_Vtl[o0] = __float2bfloat16(v0 - __bfloat162float(h0));
                    g_Vth[o1] = h1;
                    g_Vtl[o1] = __float2bfloat16(v1 - __bfloat162float(h1));
                } else {
                    uint32_t lo, hi = split_pack(v0, v1, lo);
                    size_t o = ((size_t)((b * HH + hh) * SS + sI)) * HDIM + cc;
                    __nv_bfloat16* dh = (z == 0) ? g_Qh : g_Kh;
                    __nv_bfloat16* dl = (z == 0) ? g_Ql : g_Kl;
                    *reinterpret_cast<uint32_t*>(dh + o) = hi;
                    *reinterpret_cast<uint32_t*>(dl + o) = lo;
                }
            }
        }
    }
}

// ---------------- output projection ----------------------------------------
__global__ __launch_bounds__(256, 1)
void gemm_out_mma(float* __restrict__ out)
{
    extern __shared__ char smem[];
    int rowbase = blockIdx.y * 128, colbase = blockIdx.x * 128;
    const __nv_bfloat16* Bh = g_Wh + (size_t)3 * DD * DD;
    const __nv_bfloat16* Bl = g_Wl + (size_t)3 * DD * DD;

    float d[4][4][4];
    gemm_mainloop_mma(g_Ah, g_Al, Bh, Bl, rowbase, colbase, smem, d);

    int lane = threadIdx.x & 31, warp = threadIdx.x >> 5;
    int wm = warp >> 2, wn = warp & 3;
#pragma unroll
    for (int mt = 0; mt < 4; mt++) {
        int m0 = rowbase + wm * 64 + mt * 16 + (lane >> 2);
#pragma unroll
        for (int nt = 0; nt < 4; nt++) {
            int j = colbase + wn * 32 + nt * 8 + (lane & 3) * 2;
#pragma unroll
            for (int rr = 0; rr < 2; rr++) {
                int m = m0 + rr * 8;
                float2 v = make_float2(d[mt][nt][rr * 2], d[mt][nt][rr * 2 + 1]);
                *reinterpret_cast<float2*>(out + (size_t)m * DD + j) = v;
            }
        }
    }
}

// ---------------- flash attention (mma.sync bf16 hi/lo) ---------------------
// CTA: 128 q-rows, 8 warps (m16 each), 64-key blocks, double-buffered K/V.
// smem rows padded to 144B => ldmatrix conflict-free (36i mod 32 distinct).
#define FSTR     144
#define FQ_BYTES (128 * FSTR)            // 18432 per Q matrix
#define FKV_MAT  (64 * FSTR)             // 9216 per K/V matrix
#define FST_B    (4 * FKV_MAT)           // 36864 per stage (Kh,Kl,Vth,Vtl)
#define FST_OFF  (2 * FQ_BYTES)          // 36864
#define FSMEM    (FST_OFF + 2 * FST_B)   // 110592

__global__ __launch_bounds__(256)
void flash_mma()
{
    extern __shared__ char smf[];
    uint32_t sb = smem_u32(smf);
    int tid = threadIdx.x, lane = tid & 31, w = tid >> 5;
    int bh = blockIdx.y, b = bh >> 4, h = bh & 15;
    int qt = (int)gridDim.x - 1 - (int)blockIdx.x;   // heaviest first
    int qbase = qt * 128;

    const __nv_bfloat16* Qhp = g_Qh + (size_t)bh * SS * HDIM;
    const __nv_bfloat16* Qlp = g_Ql + (size_t)bh * SS * HDIM;
    const __nv_bfloat16* Khp = g_Kh + (size_t)bh * SS * HDIM;
    const __nv_bfloat16* Klp = g_Kl + (size_t)bh * SS * HDIM;
    const __nv_bfloat16* Vhp = g_Vth + (size_t)bh * HDIM * SS;
    const __nv_bfloat16* Vlp = g_Vtl + (size_t)bh * HDIM * SS;

    // Q tile (hi+lo): 2048 cp16
#pragma unroll
    for (int t = 0; t < 8; t++) {
        int f = tid + t * 256;
        int mat = f >> 10, ww = f & 1023;
        int r = ww >> 3, c = ww & 7;
        const __nv_bfloat16* src = (mat ? Qlp : Qhp) + (size_t)(qbase + r) * HDIM + c * 8;
        cp16(sb + mat * FQ_BYTES + r * FSTR + c * 16, src);
    }
    CP_COMMIT();

    auto ldkv = [&](int s, int kb) {
#pragma unroll
        for (int t = 0; t < 8; t++) {
            int f = tid + t * 256;
            int mat = f >> 9, ww = f & 511;
            int r = ww >> 3, c = ww & 7;
            const __nv_bfloat16* src;
            if (mat == 0)      src = Khp + (size_t)(kb * 64 + r) * HDIM + c * 8;
            else if (mat == 1) src = Klp + (size_t)(kb * 64 + r) * HDIM + c * 8;
            else if (mat == 2) src = Vhp + (size_t)r * SS + kb * 64 + c * 8;
            else               src = Vlp + (size_t)r * SS + kb * 64 + c * 8;
            cp16(sb + FST_OFF + s * FST_B + mat * FKV_MAT + r * FSTR + c * 16, src);
        }
    };
    ldkv(0, 0);
    CP_COMMIT();

    float m2[2] = {-1e30f, -1e30f}, l2[2] = {0.f, 0.f};
    float o[8][4];
#pragma unroll
    for (int nt = 0; nt < 8; nt++)
#pragma unroll
        for (int e = 0; e < 4; e++) o[nt][e] = 0.f;

    int nkb = 2 * qt + 2;
    for (int kb = 0; kb < nkb; kb++) {
        if (kb + 1 < nkb) { ldkv((kb + 1) & 1, kb + 1); CP_COMMIT(); CP_WAIT(1); }
        else              { CP_WAIT(0); }
        __syncthreads();
        uint32_t st = sb + FST_OFF + (kb & 1) * FST_B;

        // ---- S = Q K^T (hi/lo 3-MMA) ----
        float sc[8][4];
#pragma unroll
        for (int nt = 0; nt < 8; nt++)
#pragma unroll
            for (int e = 0; e < 4; e++) sc[nt][e] = 0.f;

#pragma unroll
        for (int kk = 0; kk < 4; kk++) {
            uint32_t ah[4], al[4];
            uint32_t qa = sb + (w * 16 + (lane & 15)) * FSTR + (lane >> 4) * 16 + kk * 32;
            LDSM_X4(ah, qa);
            LDSM_X4(al, qa + FQ_BYTES);
#pragma unroll
            for (int nt = 0; nt < 8; nt++) {
                uint32_t ka = st + (nt * 8 + (lane & 7)) * FSTR + ((lane >> 3) & 1) * 16 + kk * 32;
                uint32_t bh_[2], bl_[2];
                LDSM_X2(bh_, ka);
                LDSM_X2(bl_, ka + FKV_MAT);
                MMA16816(sc[nt], ah, bh_);
                MMA16816(sc[nt], ah, bl_);
                MMA16816(sc[nt], al, bh_);
            }
        }

        // ---- causal mask ----
        int qr0 = qbase + w * 16 + (lane >> 2);
        if (kb * 64 + 63 > qbase + w * 16) {
#pragma unroll
            for (int nt = 0; nt < 8; nt++)
#pragma unroll
                for (int e = 0; e < 4; e++) {
                    int k = kb * 64 + nt * 8 + (lane & 3) * 2 + (e & 1);
                    int q = qr0 + (e >> 1) * 8;
                    if (k > q) sc[nt][e] = -1e30f;
                }
        }

        // ---- online softmax (fragment layout; reduce over lane quads) ----
#pragma unroll
        for (int rr = 0; rr < 2; rr++) {
            float v = -1e30f;
#pragma unroll
            for (int nt = 0; nt < 8; nt++) {
                v = fmaxf(v, sc[nt][rr * 2]);
                v = fmaxf(v, sc[nt][rr * 2 + 1]);
            }
            v = fmaxf(v, __shfl_xor_sync(0xffffffffu, v, 1));
            v = fmaxf(v, __shfl_xor_sync(0xffffffffu, v, 2));
            float mn = fmaxf(m2[rr], v);
            float alpha = __expf(m2[rr] - mn);
            float rs = 0.f;
#pragma unroll
            for (int nt = 0; nt < 8; nt++) {
                float p0 = __expf(sc[nt][rr * 2] - mn);
                float p1 = __expf(sc[nt][rr * 2 + 1] - mn);
                sc[nt][rr * 2] = p0;
                sc[nt][rr * 2 + 1] = p1;
                rs += p0 + p1;
            }
            rs += __shfl_xor_sync(0xffffffffu, rs, 1);
            rs += __shfl_xor_sync(0xffffffffu, rs, 2);
            l2[rr] = l2[rr] * alpha + rs;
            m2[rr] = mn;
#pragma unroll
            for (int nt = 0; nt < 8; nt++) {
                o[nt][rr * 2] *= alpha;
                o[nt][rr * 2 + 1] *= alpha;
            }
        }

        // ---- O += P V (P split hi/lo; S-accum frags -> A frags) ----
#pragma unroll
        for (int kk = 0; kk < 4; kk++) {
            uint32_t aph[4], apl[4];
#pragma unroll
            for (int half = 0; half < 2; half++) {
                int tile = 2 * kk + half;
#pragma unroll
                for (int rr = 0; rr < 2; rr++) {
                    uint32_t lo, hi = split_pack(sc[tile][rr * 2], sc[tile][rr * 2 + 1], lo);
                    aph[half * 2 + rr] = hi;
                    apl[half * 2 + rr] = lo;
                }
            }
#pragma unroll
            for (int nt = 0; nt < 8; nt++) {
                uint32_t va = st + 2 * FKV_MAT + (nt * 8 + (lane & 7)) * FSTR +
                              ((lane >> 3) & 1) * 16 + kk * 32;
                uint32_t vh_[2], vl_[2];
                LDSM_X2(vh_, va);
                LDSM_X2(vl_, va + FKV_MAT);
                MMA16816(o[nt], aph, vh_);
                MMA16816(o[nt], aph, vl_);
                MMA16816(o[nt], apl, vh_);
            }
        }
        __syncthreads();
    }

    // ---- epilogue: normalize, write [b][s][h*64+c] bf16 hi/lo ----
#pragma unroll
    for (int rr = 0; rr < 2; rr++) {
        float inv = 1.f / l2[rr];
        int q = qbase + w * 16 + (lane >> 2) + rr * 8;
        size_t rowo = ((size_t)b * SS + q) * DD + h * 64;
#pragma unroll
        for (int nt = 0; nt < 8; nt++) {
            int c = nt * 8 + (lane & 3) * 2;
            uint32_t lo, hi = split_pack(o[nt][rr * 2] * inv, o[nt][rr * 2 + 1] * inv, lo);
            *reinterpret_cast<uint32_t*>(g_Ah + rowo + c) = hi;
            *reinterpret_cast<uint32_t*>(g_Al + rowo + c) = lo;
        }
    }
}

// ---------------------------------------------------------------------------
extern "C" void kernel_launch(void* const* d_in, const int* in_sizes, int n_in,
                              void* d_out, int out_size)
{
    const float* x  = (const float*)d_in[0];
    const float* qw = (const float*)d_in[1];
    const float* kw = (const float*)d_in[2];
    const float* vw = (const float*)d_in[3];
    const float* ow = (const float*)d_in[4];
    float* out = (float*)d_out;

    cudaFuncSetAttribute(gemm_qkv_mma,
                         cudaFuncAttributeMaxDynamicSharedMemorySize, GSMEM);
    cudaFuncSetAttribute(gemm_out_mma,
                         cudaFuncAttributeMaxDynamicSharedMemorySize, GSMEM);
    cudaFuncSetAttribute(flash_mma,
                         cudaFuncAttributeMaxDynamicSharedMemorySize, FSMEM);

    split_x<<<MM * DD / 256, 256>>>(x);
    prep_w<<<dim3(DD / 32, DD / 32, 4), dim3(32, 32)>>>(qw, kw, vw, ow);
    gemm_qkv_mma<<<dim3(DD / 128, MM / 128, 3), 256, GSMEM>>>();
    flash_mma<<<dim3(SS / 128, BB * HH), 256, FSMEM>>>();
    gemm_out_mma<<<dim3(DD / 128, MM / 128), 256, GSMEM>>>(out);
}